// round 3
// baseline (speedup 1.0000x reference)
#include <cuda_runtime.h>
#include <math.h>

// ---------------- static config ----------------
#define CDIM   96
#define NHEAD  4
#define HDIM   24
#define NTOK   343      // tokens per window (7^3)
#define NWINS  256      // total windows (B * 4^3)
#define LTOT   21952    // 28^3
#define BATCH  4
#define MTOT   87808    // total tokens = BATCH*LTOT = NWINS*NTOK
#define HIDDEN 384
#define QSCALE 0.20412414523193154f   // 24^-0.5

// ---------------- scratch (device globals; referenced ONLY in device code) ----
__device__ float g_xw [MTOT*CDIM];                 // LN1+shift+partition output
__device__ float g_q  [NWINS*NHEAD*NTOK*HDIM];
__device__ float g_k  [NWINS*NHEAD*NTOK*HDIM];
__device__ float g_v  [NWINS*NHEAD*NTOK*HDIM];
__device__ float g_ao [MTOT*CDIM];                 // attention output (window layout)
__device__ float g_x2 [MTOT*CDIM];                 // after first residual (spatial layout)
__device__ float g_xn2[MTOT*CDIM];                 // LN2 output
__device__ float g_hbf[MTOT*HIDDEN];               // MLP hidden

// windowed token index -> (batch, spatial l) applying shift (+3 mod 28)
__device__ __forceinline__ int win_to_l(int m, int& bidx) {
    int win = m / NTOK, t = m - win * NTOK;
    bidx = win >> 6; int w3 = win & 63;
    int wh = w3 >> 4, ww = (w3 >> 2) & 3, wd = w3 & 3;
    int a = t / 49, rr = t - a * 49, bb = rr / 7, cc = rr - bb * 7;
    int gh = wh * 7 + a  + 3; if (gh >= 28) gh -= 28;
    int gw = ww * 7 + bb + 3; if (gw >= 28) gw -= 28;
    int gd = wd * 7 + cc + 3; if (gd >= 28) gd -= 28;
    return (gh * 28 + gw) * 28 + gd;
}

__device__ __forceinline__ void ln_body(const float* __restrict__ src,
                                        const float* __restrict__ w,
                                        const float* __restrict__ b,
                                        float* __restrict__ dst, int lane)
{
    float v0 = src[lane], v1 = src[lane + 32], v2 = src[lane + 64];
    float s  = v0 + v1 + v2;
    float s2 = v0 * v0 + v1 * v1 + v2 * v2;
    #pragma unroll
    for (int o = 16; o; o >>= 1) {
        s  += __shfl_xor_sync(0xffffffffu, s,  o);
        s2 += __shfl_xor_sync(0xffffffffu, s2, o);
    }
    float mu  = s * (1.0f / 96.0f);
    float var = s2 * (1.0f / 96.0f) - mu * mu;
    float rs  = rsqrtf(var + 1e-5f);
    dst[lane]      = (v0 - mu) * rs * w[lane]      + b[lane];
    dst[lane + 32] = (v1 - mu) * rs * w[lane + 32] + b[lane + 32];
    dst[lane + 64] = (v2 - mu) * rs * w[lane + 64] + b[lane + 64];
}

// LN1: reads harness x (spatial), applies shift + window-partition gather, writes g_xw
__global__ __launch_bounds__(256)
void ln1_kernel(const float* __restrict__ xin, const float* __restrict__ w,
                const float* __restrict__ b)
{
    int m    = blockIdx.x * 8 + (threadIdx.x >> 5);
    int lane = threadIdx.x & 31;
    int bidx; int l = win_to_l(m, bidx);
    const float* src = xin + ((size_t)bidx * LTOT + l) * CDIM;
    ln_body(src, w, b, g_xw + (size_t)m * CDIM, lane);
}

// LN2: g_x2 -> g_xn2 (spatial layout, no gather)
__global__ __launch_bounds__(256)
void ln2_kernel(const float* __restrict__ w, const float* __restrict__ b)
{
    int m    = blockIdx.x * 8 + (threadIdx.x >> 5);
    int lane = threadIdx.x & 31;
    ln_body(g_x2 + (size_t)m * CDIM, w, b, g_xn2 + (size_t)m * CDIM, lane);
}

// ---------------- register-tiled fp32 GEMM with fused epilogues ----------------
#define TM 64
#define KC 32
enum { EPI_QKV = 0, EPI_PROJ = 1, EPI_GELU = 2, EPI_FC2 = 3 };

__device__ __forceinline__ float gelu_exact(float x) {
    return 0.5f * x * (1.0f + erff(x * 0.70710678118654752f));
}

// A operand is selected per-EPI from device globals INSIDE device code
// (passing __device__ symbols from host passes the host shadow — the R2 bug).
template<int NCB, int EPI>
__global__ __launch_bounds__(256)
void gemm_kernel(const float* __restrict__ W,
                 const float* __restrict__ bias, int K, int Nfull,
                 const float* __restrict__ extra, float* __restrict__ outp)
{
    const float* __restrict__ A =
        (EPI == EPI_QKV)  ? g_xw  :
        (EPI == EPI_PROJ) ? g_ao  :
        (EPI == EPI_GELU) ? g_xn2 : g_hbf;

    __shared__ __align__(16) float As[TM * KC];
    __shared__ __align__(16) float Ws[KC * NCB];
    const int tx  = threadIdx.x;            // 0 .. NCB/4-1
    const int ty  = threadIdx.y;            // 0 .. 7
    const int nth = (NCB / 4) * 8;
    const int tid = ty * (NCB / 4) + tx;
    const int m0  = blockIdx.x * TM;
    const int n0  = blockIdx.y * NCB;

    float4 acc[8];
    #pragma unroll
    for (int r = 0; r < 8; r++) acc[r] = make_float4(0.f, 0.f, 0.f, 0.f);

    for (int k0 = 0; k0 < K; k0 += KC) {
        for (int idx = tid; idx < TM * KC; idx += nth) {
            int r = idx >> 5, c = idx & 31;
            As[idx] = A[(size_t)(m0 + r) * K + k0 + c];
        }
        for (int idx = tid; idx < KC * NCB; idx += nth) {
            int r = idx / NCB, c = idx - r * NCB;
            Ws[idx] = W[(size_t)(k0 + r) * Nfull + n0 + c];
        }
        __syncthreads();
        #pragma unroll 4
        for (int kk = 0; kk < KC; kk++) {
            float4 w4 = *reinterpret_cast<float4*>(&Ws[kk * NCB + 4 * tx]);
            #pragma unroll
            for (int r = 0; r < 8; r++) {
                float a = As[(ty * 8 + r) * KC + kk];
                acc[r].x = fmaf(a, w4.x, acc[r].x);
                acc[r].y = fmaf(a, w4.y, acc[r].y);
                acc[r].z = fmaf(a, w4.z, acc[r].z);
                acc[r].w = fmaf(a, w4.w, acc[r].w);
            }
        }
        __syncthreads();
    }

    const int j = n0 + 4 * tx;
    const float4 bv = *reinterpret_cast<const float4*>(&bias[j]);

    // hoisted QKV decode (constant per thread; dead for non-QKV EPI)
    int chunk = j / 96;
    int within = j - chunk * 96;
    int hh = within / 24;
    int dd = within - hh * 24;
    float* qkv_dst = (chunk == 0) ? g_q : (chunk == 1 ? g_k : g_v);

    #pragma unroll
    for (int r = 0; r < 8; r++) {
        int m = m0 + ty * 8 + r;
        float4 v = make_float4(acc[r].x + bv.x, acc[r].y + bv.y,
                               acc[r].z + bv.z, acc[r].w + bv.w);
        if (EPI == EPI_QKV) {
            if (chunk == 0) { v.x *= QSCALE; v.y *= QSCALE; v.z *= QSCALE; v.w *= QSCALE; }
            int win = m / NTOK, t = m - win * NTOK;
            size_t off = (((size_t)(win * NHEAD + hh)) * NTOK + t) * HDIM + dd;
            *reinterpret_cast<float4*>(&qkv_dst[off]) = v;
        } else if (EPI == EPI_PROJ) {
            int bidx; int l = win_to_l(m, bidx);
            size_t off = ((size_t)bidx * LTOT + l) * CDIM + j;
            const float4 sc = *reinterpret_cast<const float4*>(&extra[off]);
            v.x += sc.x; v.y += sc.y; v.z += sc.z; v.w += sc.w;
            *reinterpret_cast<float4*>(&g_x2[off]) = v;
        } else if (EPI == EPI_GELU) {
            v.x = gelu_exact(v.x); v.y = gelu_exact(v.y);
            v.z = gelu_exact(v.z); v.w = gelu_exact(v.w);
            *reinterpret_cast<float4*>(&g_hbf[(size_t)m * HIDDEN + j]) = v;
        } else { // EPI_FC2: + residual(g_x2) -> final out
            size_t off = (size_t)m * CDIM + j;
            const float4 sc = *reinterpret_cast<const float4*>(&g_x2[off]);
            v.x += sc.x; v.y += sc.y; v.z += sc.z; v.w += sc.w;
            *reinterpret_cast<float4*>(&outp[off]) = v;
        }
    }
}

// ---------------- fused windowed attention ----------------
// one block per (window, head); analytic RPB index + shift mask; online softmax
#define ATTN_THREADS 352
#define ATTN_SMEM ((8232*2 + 328 + 343 + 343) * 4)   // 69912 bytes

__global__ __launch_bounds__(ATTN_THREADS)
void attn_kernel(const float* __restrict__ rpb_table)
{
    extern __shared__ float sm[];
    float* ks   = sm;                 // 343*24
    float* vs   = sm + 8232;          // 343*24
    float* rpbs = vs + 8232;          // 325 used, 328 reserved
    int*   keys = (int*)(rpbs + 328); // 343
    int*   grps = keys + 343;         // 343

    const int bh  = blockIdx.x;       // win*4 + head
    const int win = bh >> 2, h = bh & 3;
    const int tid = threadIdx.x;

    size_t base = (size_t)bh * (NTOK * HDIM);
    for (int idx = tid; idx < NTOK * HDIM; idx += ATTN_THREADS) {
        ks[idx] = g_k[base + idx];
        vs[idx] = g_v[base + idx];
    }
    for (int idx = tid; idx < 325; idx += ATTN_THREADS)
        rpbs[idx] = rpb_table[idx * NHEAD + h];

    int w3 = win & 63;
    int wh = w3 >> 4, ww = (w3 >> 2) & 3, wd = w3 & 3;
    for (int t = tid; t < NTOK; t += ATTN_THREADS) {
        int a = t / 49, rr = t - a * 49, bb = rr / 7, cc = rr - bb * 7;
        keys[t] = 13 * (a + bb) + cc;
        int gh = wh * 7 + a, gw = ww * 7 + bb, gd = wd * 7 + cc;
        int sg = ((gh >= 21) + (gh >= 25)) * 9
               + ((gw >= 21) + (gw >= 25)) * 3
               + ((gd >= 21) + (gd >= 25));
        grps[t] = sg;
    }
    __syncthreads();

    if (tid >= NTOK) return;

    float q[HDIM];
    const float* qp = g_q + base + tid * HDIM;
    #pragma unroll
    for (int d = 0; d < HDIM; d++) q[d] = qp[d];

    const int key_i = keys[tid] + 162;
    const int grp_i = grps[tid];

    float mmax = -1e30f, ssum = 0.0f;
    float acc[HDIM];
    #pragma unroll
    for (int d = 0; d < HDIM; d++) acc[d] = 0.0f;

    for (int jt = 0; jt < NTOK; jt++) {
        const float* kr = &ks[jt * HDIM];
        float dot = 0.0f;
        #pragma unroll
        for (int d = 0; d < HDIM; d++) dot = fmaf(q[d], kr[d], dot);
        float s = dot + rpbs[key_i - keys[jt]];
        if (grp_i != grps[jt]) s -= 100.0f;
        float p;
        if (s > mmax) {                       // rare rescale
            float c = __expf(mmax - s);
            ssum *= c;
            #pragma unroll
            for (int d = 0; d < HDIM; d++) acc[d] *= c;
            mmax = s; p = 1.0f;
        } else {
            p = __expf(s - mmax);
        }
        ssum += p;
        const float* vr = &vs[jt * HDIM];
        #pragma unroll
        for (int d = 0; d < HDIM; d++) acc[d] = fmaf(p, vr[d], acc[d]);
    }

    float inv = 1.0f / ssum;
    float* op = g_ao + ((size_t)win * NTOK + tid) * CDIM + h * HDIM;
    #pragma unroll
    for (int d = 0; d < HDIM; d++) op[d] = acc[d] * inv;
}

// ---------------- launch ----------------
extern "C" void kernel_launch(void* const* d_in, const int* in_sizes, int n_in,
                              void* d_out, int out_size)
{
    const float* x    = (const float*)d_in[0];
    const float* n1w  = (const float*)d_in[1];
    const float* n1b  = (const float*)d_in[2];
    const float* qkvw = (const float*)d_in[3];
    const float* qkvb = (const float*)d_in[4];
    const float* rpb  = (const float*)d_in[5];
    const float* pw   = (const float*)d_in[6];
    const float* pb   = (const float*)d_in[7];
    const float* n2w  = (const float*)d_in[8];
    const float* n2b  = (const float*)d_in[9];
    const float* f1w  = (const float*)d_in[10];
    const float* f1b  = (const float*)d_in[11];
    const float* f2w  = (const float*)d_in[12];
    const float* f2b  = (const float*)d_in[13];
    float* out = (float*)d_out;

    cudaFuncSetAttribute(attn_kernel, cudaFuncAttributeMaxDynamicSharedMemorySize, ATTN_SMEM);

    // 1) LN1 + shift + window partition -> g_xw
    ln1_kernel<<<MTOT / 8, 256>>>(x, n1w, n1b);
    // 2) QKV projection (M=87808, K=96, N=288) -> g_q/g_k/g_v
    gemm_kernel<96, EPI_QKV><<<dim3(MTOT / TM, 3), dim3(24, 8)>>>(
        qkvw, qkvb, 96, 288, nullptr, nullptr);
    // 3) windowed attention (256 windows x 4 heads) -> g_ao
    attn_kernel<<<NWINS * NHEAD, ATTN_THREADS, ATTN_SMEM>>>(rpb);
    // 4) proj + window reverse + unshift + residual(x) -> g_x2
    gemm_kernel<96, EPI_PROJ><<<dim3(MTOT / TM, 1), dim3(24, 8)>>>(
        pw, pb, 96, 96, x, nullptr);
    // 5) LN2: g_x2 -> g_xn2
    ln2_kernel<<<MTOT / 8, 256>>>(n2w, n2b);
    // 6) fc1 + exact GELU (K=96, N=384) -> g_hbf
    gemm_kernel<128, EPI_GELU><<<dim3(MTOT / TM, 3), dim3(32, 8)>>>(
        f1w, f1b, 96, 384, nullptr, nullptr);
    // 7) fc2 + residual(g_x2) -> d_out (K=384, N=96)
    gemm_kernel<96, EPI_FC2><<<dim3(MTOT / TM, 1), dim3(24, 8)>>>(
        f2w, f2b, 384, 96, nullptr, out);
}

// round 5
// speedup vs baseline: 1.8119x; 1.8119x over previous
#include <cuda_runtime.h>
#include <cuda_bf16.h>
#include <cstdint>
#include <math.h>

// ---------------- static config ----------------
#define CDIM   96
#define NHEAD  4
#define HDIM   24
#define NTOK   343
#define NWINS  256
#define LTOT   21952
#define MTOT   87808
#define HIDDEN 384
#define QSCALE 0.20412414523193154f

// ---------------- scratch (device globals; referenced ONLY in device code) ----
__device__ __nv_bfloat16 g_xw [MTOT*CDIM];       // LN1 out (bf16, window layout)
__device__ float         g_q  [NWINS*NHEAD*NTOK*HDIM];
__device__ float         g_k  [NWINS*NHEAD*NTOK*HDIM];
__device__ float         g_v  [NWINS*NHEAD*NTOK*HDIM];
__device__ __nv_bfloat16 g_ao [MTOT*CDIM];       // attn out (bf16, window layout)
__device__ float         g_x2 [MTOT*CDIM];       // residual 1 (fp32, spatial)
__device__ __nv_bfloat16 g_xn2[MTOT*CDIM];       // LN2 out (bf16, spatial)
__device__ __nv_bfloat16 g_hbf[MTOT*HIDDEN];     // MLP hidden (bf16)
// transposed bf16 weights Wt[n][k]
__device__ __nv_bfloat16 g_wq[288*96];
__device__ __nv_bfloat16 g_wp[96*96];
__device__ __nv_bfloat16 g_w1[384*96];
__device__ __nv_bfloat16 g_w2[96*384];

// windowed token index -> (batch, spatial l) applying shift (+3 mod 28)
__device__ __forceinline__ int win_to_l(int m, int& bidx) {
    int win = m / NTOK, t = m - win * NTOK;
    bidx = win >> 6; int w3 = win & 63;
    int wh = w3 >> 4, ww = (w3 >> 2) & 3, wd = w3 & 3;
    int a = t / 49, rr = t - a * 49, bb = rr / 7, cc = rr - bb * 7;
    int gh = wh * 7 + a  + 3; if (gh >= 28) gh -= 28;
    int gw = ww * 7 + bb + 3; if (gw >= 28) gw -= 28;
    int gd = wd * 7 + cc + 3; if (gd >= 28) gd -= 28;
    return (gh * 28 + gw) * 28 + gd;
}

// ---------------- weight prep: transpose + bf16 ----------------
__global__ __launch_bounds__(256)
void prep_weights(const float* __restrict__ qkvw, const float* __restrict__ pw,
                  const float* __restrict__ f1w,  const float* __restrict__ f2w)
{
    int i = blockIdx.x * 256 + threadIdx.x;
    if (i < 288*96) { int n = i / 96,  k = i - n*96;  g_wq[i] = __float2bfloat16(qkvw[k*288 + n]); }
    if (i < 96*96)  { int n = i / 96,  k = i - n*96;  g_wp[i] = __float2bfloat16(pw  [k*96  + n]); }
    if (i < 384*96) { int n = i / 96,  k = i - n*96;  g_w1[i] = __float2bfloat16(f1w [k*384 + n]); }
    if (i < 96*384) { int n = i / 384, k = i - n*384; g_w2[i] = __float2bfloat16(f2w [k*96  + n]); }
}

// ---------------- LayerNorm (warp per token) ----------------
__device__ __forceinline__ void ln_body(const float* __restrict__ src,
                                        const float* __restrict__ w,
                                        const float* __restrict__ b,
                                        __nv_bfloat16* __restrict__ dst, int lane)
{
    float v0 = src[lane], v1 = src[lane + 32], v2 = src[lane + 64];
    float s  = v0 + v1 + v2;
    float s2 = v0 * v0 + v1 * v1 + v2 * v2;
    #pragma unroll
    for (int o = 16; o; o >>= 1) {
        s  += __shfl_xor_sync(0xffffffffu, s,  o);
        s2 += __shfl_xor_sync(0xffffffffu, s2, o);
    }
    float mu  = s * (1.0f / 96.0f);
    float var = s2 * (1.0f / 96.0f) - mu * mu;
    float rs  = rsqrtf(var + 1e-5f);
    dst[lane]      = __float2bfloat16((v0 - mu) * rs * w[lane]      + b[lane]);
    dst[lane + 32] = __float2bfloat16((v1 - mu) * rs * w[lane + 32] + b[lane + 32]);
    dst[lane + 64] = __float2bfloat16((v2 - mu) * rs * w[lane + 64] + b[lane + 64]);
}

__global__ __launch_bounds__(256)
void ln1_kernel(const float* __restrict__ xin, const float* __restrict__ w,
                const float* __restrict__ b)
{
    int m = blockIdx.x * 8 + (threadIdx.x >> 5);
    int lane = threadIdx.x & 31;
    int bidx; int l = win_to_l(m, bidx);
    ln_body(xin + ((size_t)bidx * LTOT + l) * CDIM, w, b, g_xw + (size_t)m * CDIM, lane);
}

__global__ __launch_bounds__(256)
void ln2_kernel(const float* __restrict__ w, const float* __restrict__ b)
{
    int m = blockIdx.x * 8 + (threadIdx.x >> 5);
    int lane = threadIdx.x & 31;
    ln_body(g_x2 + (size_t)m * CDIM, w, b, g_xn2 + (size_t)m * CDIM, lane);
}

// ---------------- bf16 HMMA GEMM (m16n8k16) with fused epilogues ----------------
enum { EPI_QKV = 0, EPI_PROJ = 1, EPI_GELU = 2, EPI_FC2 = 3 };
#define ASTR 104   // smem stride in halfwords (bank-conflict-free: 52 mod 32 = 20)

__device__ __forceinline__ float gelu_exact(float x) {
    return 0.5f * x * (1.0f + erff(x * 0.70710678118654752f));
}

__device__ __forceinline__ void mma16816(float c[4],
    uint32_t a0, uint32_t a1, uint32_t a2, uint32_t a3, uint32_t b0, uint32_t b1)
{
    asm volatile(
        "mma.sync.aligned.m16n8k16.row.col.f32.bf16.bf16.f32 "
        "{%0,%1,%2,%3},{%4,%5,%6,%7},{%8,%9},{%0,%1,%2,%3};\n"
        : "+f"(c[0]), "+f"(c[1]), "+f"(c[2]), "+f"(c[3])
        : "r"(a0), "r"(a1), "r"(a2), "r"(a3), "r"(b0), "r"(b1));
}

template<int EPI>
__device__ __forceinline__ void store2(int m, int j0, float v0, float v1,
                                       const float* __restrict__ extra,
                                       float* __restrict__ outp)
{
    if (EPI == EPI_QKV) {
        int chunk = j0 / 96, within = j0 - chunk * 96;
        int hh = within / 24, dd = within - hh * 24;
        float* dst = (chunk == 0) ? g_q : (chunk == 1 ? g_k : g_v);
        if (chunk == 0) { v0 *= QSCALE; v1 *= QSCALE; }
        int win = m / NTOK, t = m - win * NTOK;
        size_t off = (((size_t)(win * NHEAD + hh)) * NTOK + t) * HDIM + dd;
        *reinterpret_cast<float2*>(&dst[off]) = make_float2(v0, v1);
    } else if (EPI == EPI_PROJ) {
        int bidx; int l = win_to_l(m, bidx);
        size_t off = ((size_t)bidx * LTOT + l) * CDIM + j0;
        float2 sc = *reinterpret_cast<const float2*>(&extra[off]);
        *reinterpret_cast<float2*>(&g_x2[off]) = make_float2(v0 + sc.x, v1 + sc.y);
    } else if (EPI == EPI_GELU) {
        __nv_bfloat162 h;
        h.x = __float2bfloat16(gelu_exact(v0));
        h.y = __float2bfloat16(gelu_exact(v1));
        *reinterpret_cast<__nv_bfloat162*>(&g_hbf[(size_t)m * HIDDEN + j0]) = h;
    } else { // EPI_FC2
        size_t off = (size_t)m * CDIM + j0;
        float2 sc = *reinterpret_cast<const float2*>(&g_x2[off]);
        *reinterpret_cast<float2*>(&outp[off]) = make_float2(v0 + sc.x, v1 + sc.y);
    }
}

// Block tile 128x32, 8 warps (warp tile 16x32), BK=96.
template<int EPI, int KF, int NF>
__global__ __launch_bounds__(256)
void hgemm_kernel(const float* __restrict__ bias,
                  const float* __restrict__ extra, float* __restrict__ outp)
{
    const __nv_bfloat16* __restrict__ A =
        (EPI == EPI_QKV)  ? g_xw  :
        (EPI == EPI_PROJ) ? g_ao  :
        (EPI == EPI_GELU) ? g_xn2 : g_hbf;
    const __nv_bfloat16* __restrict__ Wt =
        (EPI == EPI_QKV)  ? g_wq  :
        (EPI == EPI_PROJ) ? g_wp  :
        (EPI == EPI_GELU) ? g_w1  : g_w2;

    __shared__ __nv_bfloat16 As[128 * ASTR];
    __shared__ __nv_bfloat16 Ws[32 * ASTR];

    const int tid  = threadIdx.x;
    const int warp = tid >> 5, lane = tid & 31;
    const int m0 = blockIdx.x * 128, n0 = blockIdx.y * 32;
    const int l4 = lane >> 2, q2 = (lane & 3) * 2;

    float c[4][4] = {};

    for (int k0 = 0; k0 < KF; k0 += 96) {
        // A tile 128x96 bf16 (uint4 = 8 bf16; smem rows 8B-aligned -> 2x uint2)
        #pragma unroll
        for (int e = tid; e < 128 * 12; e += 256) {
            int row = e / 12, c8 = (e - row * 12) * 8;
            uint4 val = *reinterpret_cast<const uint4*>(&A[(size_t)(m0 + row) * KF + k0 + c8]);
            uint2* dst = reinterpret_cast<uint2*>(&As[row * ASTR + c8]);
            dst[0] = make_uint2(val.x, val.y);
            dst[1] = make_uint2(val.z, val.w);
        }
        // W tile 32x96 (pre-transposed Wt[n][k])
        for (int e = tid; e < 32 * 12; e += 256) {
            int row = e / 12, c8 = (e - row * 12) * 8;
            uint4 val = *reinterpret_cast<const uint4*>(&Wt[(size_t)(n0 + row) * KF + k0 + c8]);
            uint2* dst = reinterpret_cast<uint2*>(&Ws[row * ASTR + c8]);
            dst[0] = make_uint2(val.x, val.y);
            dst[1] = make_uint2(val.z, val.w);
        }
        __syncthreads();
        #pragma unroll
        for (int s = 0; s < 6; s++) {
            const int kb = s * 16;
            uint32_t a0 = *reinterpret_cast<const uint32_t*>(&As[(warp*16 + l4    ) * ASTR + kb + q2]);
            uint32_t a1 = *reinterpret_cast<const uint32_t*>(&As[(warp*16 + l4 + 8) * ASTR + kb + q2]);
            uint32_t a2 = *reinterpret_cast<const uint32_t*>(&As[(warp*16 + l4    ) * ASTR + kb + 8 + q2]);
            uint32_t a3 = *reinterpret_cast<const uint32_t*>(&As[(warp*16 + l4 + 8) * ASTR + kb + 8 + q2]);
            #pragma unroll
            for (int nt = 0; nt < 4; nt++) {
                uint32_t b0 = *reinterpret_cast<const uint32_t*>(&Ws[(nt*8 + l4) * ASTR + kb + q2]);
                uint32_t b1 = *reinterpret_cast<const uint32_t*>(&Ws[(nt*8 + l4) * ASTR + kb + 8 + q2]);
                mma16816(c[nt], a0, a1, a2, a3, b0, b1);
            }
        }
        __syncthreads();
    }

    const int mr = m0 + warp * 16 + l4;
    #pragma unroll
    for (int nt = 0; nt < 4; nt++) {
        int j0 = n0 + nt * 8 + q2;
        float bv0 = bias[j0], bv1 = bias[j0 + 1];
        store2<EPI>(mr,     j0, c[nt][0] + bv0, c[nt][1] + bv1, extra, outp);
        store2<EPI>(mr + 8, j0, c[nt][2] + bv0, c[nt][3] + bv1, extra, outp);
    }
}

// ---------------- fused windowed attention (fp32, unchanged core) ----------------
#define ATTN_THREADS 352
#define ATTN_SMEM ((8232*2 + 328 + 343 + 343) * 4)

__global__ __launch_bounds__(ATTN_THREADS)
void attn_kernel(const float* __restrict__ rpb_table)
{
    extern __shared__ float sm[];
    float* ks   = sm;
    float* vs   = sm + 8232;
    float* rpbs = vs + 8232;
    int*   keys = (int*)(rpbs + 328);
    int*   grps = keys + 343;

    const int bh  = blockIdx.x;
    const int win = bh >> 2, h = bh & 3;
    const int tid = threadIdx.x;

    size_t base = (size_t)bh * (NTOK * HDIM);
    for (int idx = tid; idx < NTOK * HDIM; idx += ATTN_THREADS) {
        ks[idx] = g_k[base + idx];
        vs[idx] = g_v[base + idx];
    }
    for (int idx = tid; idx < 325; idx += ATTN_THREADS)
        rpbs[idx] = rpb_table[idx * NHEAD + h];

    int w3 = win & 63;
    int wh = w3 >> 4, ww = (w3 >> 2) & 3, wd = w3 & 3;
    for (int t = tid; t < NTOK; t += ATTN_THREADS) {
        int a = t / 49, rr = t - a * 49, bb = rr / 7, cc = rr - bb * 7;
        keys[t] = 13 * (a + bb) + cc;
        int gh = wh * 7 + a, gw = ww * 7 + bb, gd = wd * 7 + cc;
        grps[t] = ((gh >= 21) + (gh >= 25)) * 9
                + ((gw >= 21) + (gw >= 25)) * 3
                + ((gd >= 21) + (gd >= 25));
    }
    __syncthreads();

    if (tid >= NTOK) return;

    float q[HDIM];
    const float* qp = g_q + base + tid * HDIM;
    #pragma unroll
    for (int d = 0; d < HDIM; d++) q[d] = qp[d];

    const int key_i = keys[tid] + 162;
    const int grp_i = grps[tid];

    float mmax = -1e30f, ssum = 0.0f;
    float acc[HDIM];
    #pragma unroll
    for (int d = 0; d < HDIM; d++) acc[d] = 0.0f;

    for (int jt = 0; jt < NTOK; jt++) {
        const float* kr = &ks[jt * HDIM];
        float dot = 0.0f;
        #pragma unroll
        for (int d = 0; d < HDIM; d++) dot = fmaf(q[d], kr[d], dot);
        float s = dot + rpbs[key_i - keys[jt]];
        if (grp_i != grps[jt]) s -= 100.0f;
        float p;
        if (s > mmax) {
            float cc = __expf(mmax - s);
            ssum *= cc;
            #pragma unroll
            for (int d = 0; d < HDIM; d++) acc[d] *= cc;
            mmax = s; p = 1.0f;
        } else {
            p = __expf(s - mmax);
        }
        ssum += p;
        const float* vr = &vs[jt * HDIM];
        #pragma unroll
        for (int d = 0; d < HDIM; d++) acc[d] = fmaf(p, vr[d], acc[d]);
    }

    float inv = 1.0f / ssum;
    __nv_bfloat16* op = g_ao + ((size_t)win * NTOK + tid) * CDIM + h * HDIM;
    #pragma unroll
    for (int d = 0; d < HDIM; d++) op[d] = __float2bfloat16(acc[d] * inv);
}

// ---------------- launch ----------------
extern "C" void kernel_launch(void* const* d_in, const int* in_sizes, int n_in,
                              void* d_out, int out_size)
{
    const float* x    = (const float*)d_in[0];
    const float* n1w  = (const float*)d_in[1];
    const float* n1b  = (const float*)d_in[2];
    const float* qkvw = (const float*)d_in[3];
    const float* qkvb = (const float*)d_in[4];
    const float* rpb  = (const float*)d_in[5];
    const float* pw   = (const float*)d_in[6];
    const float* pb   = (const float*)d_in[7];
    const float* n2w  = (const float*)d_in[8];
    const float* n2b  = (const float*)d_in[9];
    const float* f1w  = (const float*)d_in[10];
    const float* f1b  = (const float*)d_in[11];
    const float* f2w  = (const float*)d_in[12];
    const float* f2b  = (const float*)d_in[13];
    float* out = (float*)d_out;

    cudaFuncSetAttribute(attn_kernel, cudaFuncAttributeMaxDynamicSharedMemorySize, ATTN_SMEM);

    prep_weights<<<144, 256>>>(qkvw, pw, f1w, f2w);
    ln1_kernel<<<MTOT / 8, 256>>>(x, n1w, n1b);
    hgemm_kernel<EPI_QKV, 96, 288><<<dim3(686, 9), 256>>>(qkvb, nullptr, nullptr);
    attn_kernel<<<NWINS * NHEAD, ATTN_THREADS, ATTN_SMEM>>>(rpb);
    hgemm_kernel<EPI_PROJ, 96, 96><<<dim3(686, 3), 256>>>(pb, x, nullptr);
    ln2_kernel<<<MTOT / 8, 256>>>(n2w, n2b);
    hgemm_kernel<EPI_GELU, 96, 384><<<dim3(686, 12), 256>>>(f1b, nullptr, nullptr);
    hgemm_kernel<EPI_FC2, 384, 96><<<dim3(686, 3), 256>>>(f2b, nullptr, out);
}

// round 6
// speedup vs baseline: 3.8464x; 2.1228x over previous
#include <cuda_runtime.h>
#include <cuda_bf16.h>
#include <cstdint>
#include <math.h>

// ---------------- static config ----------------
#define CDIM   96
#define NHEAD  4
#define HDIM   24
#define NTOK   343
#define NWINS  256
#define LTOT   21952
#define MTOT   87808
#define HIDDEN 384
#define QSCALE 0.20412414523193154f

// ---------------- scratch (device globals; referenced ONLY in device code) ----
__device__ __nv_bfloat16 g_xw [MTOT*CDIM];       // LN1 out (bf16, window layout)
__device__ __nv_bfloat16 g_q  [NWINS*NHEAD*NTOK*HDIM];   // bf16, pre-scaled
__device__ __nv_bfloat16 g_k  [NWINS*NHEAD*NTOK*HDIM];
__device__ __nv_bfloat16 g_v  [NWINS*NHEAD*NTOK*HDIM];
__device__ __nv_bfloat16 g_ao [MTOT*CDIM];       // attn out (bf16, window layout)
__device__ float         g_x2 [MTOT*CDIM];       // residual 1 (fp32, spatial)
__device__ __nv_bfloat16 g_xn2[MTOT*CDIM];       // LN2 out (bf16, spatial)
__device__ __nv_bfloat16 g_hbf[MTOT*HIDDEN];     // MLP hidden (bf16)
// transposed bf16 weights Wt[n][k]
__device__ __nv_bfloat16 g_wq[288*96];
__device__ __nv_bfloat16 g_wp[96*96];
__device__ __nv_bfloat16 g_w1[384*96];
__device__ __nv_bfloat16 g_w2[96*384];

// windowed token index -> (batch, spatial l) applying shift (+3 mod 28)
__device__ __forceinline__ int win_to_l(int m, int& bidx) {
    int win = m / NTOK, t = m - win * NTOK;
    bidx = win >> 6; int w3 = win & 63;
    int wh = w3 >> 4, ww = (w3 >> 2) & 3, wd = w3 & 3;
    int a = t / 49, rr = t - a * 49, bb = rr / 7, cc = rr - bb * 7;
    int gh = wh * 7 + a  + 3; if (gh >= 28) gh -= 28;
    int gw = ww * 7 + bb + 3; if (gw >= 28) gw -= 28;
    int gd = wd * 7 + cc + 3; if (gd >= 28) gd -= 28;
    return (gh * 28 + gw) * 28 + gd;
}

// ---------------- weight prep: transpose + bf16 ----------------
__global__ __launch_bounds__(256)
void prep_weights(const float* __restrict__ qkvw, const float* __restrict__ pw,
                  const float* __restrict__ f1w,  const float* __restrict__ f2w)
{
    int i = blockIdx.x * 256 + threadIdx.x;
    if (i < 288*96) { int n = i / 96,  k = i - n*96;  g_wq[i] = __float2bfloat16(qkvw[k*288 + n]); }
    if (i < 96*96)  { int n = i / 96,  k = i - n*96;  g_wp[i] = __float2bfloat16(pw  [k*96  + n]); }
    if (i < 384*96) { int n = i / 96,  k = i - n*96;  g_w1[i] = __float2bfloat16(f1w [k*384 + n]); }
    if (i < 96*384) { int n = i / 384, k = i - n*384; g_w2[i] = __float2bfloat16(f2w [k*96  + n]); }
}

// ---------------- LayerNorm (warp per token) ----------------
__device__ __forceinline__ void ln_body(const float* __restrict__ src,
                                        const float* __restrict__ w,
                                        const float* __restrict__ b,
                                        __nv_bfloat16* __restrict__ dst, int lane)
{
    float v0 = src[lane], v1 = src[lane + 32], v2 = src[lane + 64];
    float s  = v0 + v1 + v2;
    float s2 = v0 * v0 + v1 * v1 + v2 * v2;
    #pragma unroll
    for (int o = 16; o; o >>= 1) {
        s  += __shfl_xor_sync(0xffffffffu, s,  o);
        s2 += __shfl_xor_sync(0xffffffffu, s2, o);
    }
    float mu  = s * (1.0f / 96.0f);
    float var = s2 * (1.0f / 96.0f) - mu * mu;
    float rs  = rsqrtf(var + 1e-5f);
    dst[lane]      = __float2bfloat16((v0 - mu) * rs * w[lane]      + b[lane]);
    dst[lane + 32] = __float2bfloat16((v1 - mu) * rs * w[lane + 32] + b[lane + 32]);
    dst[lane + 64] = __float2bfloat16((v2 - mu) * rs * w[lane + 64] + b[lane + 64]);
}

__global__ __launch_bounds__(256)
void ln1_kernel(const float* __restrict__ xin, const float* __restrict__ w,
                const float* __restrict__ b)
{
    int m = blockIdx.x * 8 + (threadIdx.x >> 5);
    int lane = threadIdx.x & 31;
    int bidx; int l = win_to_l(m, bidx);
    ln_body(xin + ((size_t)bidx * LTOT + l) * CDIM, w, b, g_xw + (size_t)m * CDIM, lane);
}

__global__ __launch_bounds__(256)
void ln2_kernel(const float* __restrict__ w, const float* __restrict__ b)
{
    int m = blockIdx.x * 8 + (threadIdx.x >> 5);
    int lane = threadIdx.x & 31;
    ln_body(g_x2 + (size_t)m * CDIM, w, b, g_xn2 + (size_t)m * CDIM, lane);
}

// ---------------- bf16 HMMA GEMM (m16n8k16) with fused epilogues ----------------
enum { EPI_QKV = 0, EPI_PROJ = 1, EPI_GELU = 2, EPI_FC2 = 3 };
#define ASTR 104

__device__ __forceinline__ float gelu_exact(float x) {
    return 0.5f * x * (1.0f + erff(x * 0.70710678118654752f));
}

__device__ __forceinline__ void mma16816(float c[4],
    uint32_t a0, uint32_t a1, uint32_t a2, uint32_t a3, uint32_t b0, uint32_t b1)
{
    asm volatile(
        "mma.sync.aligned.m16n8k16.row.col.f32.bf16.bf16.f32 "
        "{%0,%1,%2,%3},{%4,%5,%6,%7},{%8,%9},{%0,%1,%2,%3};\n"
        : "+f"(c[0]), "+f"(c[1]), "+f"(c[2]), "+f"(c[3])
        : "r"(a0), "r"(a1), "r"(a2), "r"(a3), "r"(b0), "r"(b1));
}

template<int EPI>
__device__ __forceinline__ void store2(int m, int j0, float v0, float v1,
                                       const float* __restrict__ extra,
                                       float* __restrict__ outp)
{
    if (EPI == EPI_QKV) {
        int chunk = j0 / 96, within = j0 - chunk * 96;
        int hh = within / 24, dd = within - hh * 24;
        __nv_bfloat16* dst = (chunk == 0) ? g_q : (chunk == 1 ? g_k : g_v);
        if (chunk == 0) { v0 *= QSCALE; v1 *= QSCALE; }
        int win = m / NTOK, t = m - win * NTOK;
        size_t off = (((size_t)(win * NHEAD + hh)) * NTOK + t) * HDIM + dd;
        *reinterpret_cast<__nv_bfloat162*>(&dst[off]) =
            __float22bfloat162_rn(make_float2(v0, v1));
    } else if (EPI == EPI_PROJ) {
        int bidx; int l = win_to_l(m, bidx);
        size_t off = ((size_t)bidx * LTOT + l) * CDIM + j0;
        float2 sc = *reinterpret_cast<const float2*>(&extra[off]);
        *reinterpret_cast<float2*>(&g_x2[off]) = make_float2(v0 + sc.x, v1 + sc.y);
    } else if (EPI == EPI_GELU) {
        __nv_bfloat162 h;
        h.x = __float2bfloat16(gelu_exact(v0));
        h.y = __float2bfloat16(gelu_exact(v1));
        *reinterpret_cast<__nv_bfloat162*>(&g_hbf[(size_t)m * HIDDEN + j0]) = h;
    } else { // EPI_FC2
        size_t off = (size_t)m * CDIM + j0;
        float2 sc = *reinterpret_cast<const float2*>(&g_x2[off]);
        *reinterpret_cast<float2*>(&outp[off]) = make_float2(v0 + sc.x, v1 + sc.y);
    }
}

// Block tile 128x32, 8 warps (warp tile 16x32), BK=96.
template<int EPI, int KF, int NF>
__global__ __launch_bounds__(256)
void hgemm_kernel(const float* __restrict__ bias,
                  const float* __restrict__ extra, float* __restrict__ outp)
{
    const __nv_bfloat16* __restrict__ A =
        (EPI == EPI_QKV)  ? g_xw  :
        (EPI == EPI_PROJ) ? g_ao  :
        (EPI == EPI_GELU) ? g_xn2 : g_hbf;
    const __nv_bfloat16* __restrict__ Wt =
        (EPI == EPI_QKV)  ? g_wq  :
        (EPI == EPI_PROJ) ? g_wp  :
        (EPI == EPI_GELU) ? g_w1  : g_w2;

    __shared__ __nv_bfloat16 As[128 * ASTR];
    __shared__ __nv_bfloat16 Ws[32 * ASTR];

    const int tid  = threadIdx.x;
    const int warp = tid >> 5, lane = tid & 31;
    const int m0 = blockIdx.x * 128, n0 = blockIdx.y * 32;
    const int l4 = lane >> 2, q2 = (lane & 3) * 2;

    float c[4][4] = {};

    for (int k0 = 0; k0 < KF; k0 += 96) {
        #pragma unroll
        for (int e = tid; e < 128 * 12; e += 256) {
            int row = e / 12, c8 = (e - row * 12) * 8;
            uint4 val = *reinterpret_cast<const uint4*>(&A[(size_t)(m0 + row) * KF + k0 + c8]);
            uint2* dst = reinterpret_cast<uint2*>(&As[row * ASTR + c8]);
            dst[0] = make_uint2(val.x, val.y);
            dst[1] = make_uint2(val.z, val.w);
        }
        for (int e = tid; e < 32 * 12; e += 256) {
            int row = e / 12, c8 = (e - row * 12) * 8;
            uint4 val = *reinterpret_cast<const uint4*>(&Wt[(size_t)(n0 + row) * KF + k0 + c8]);
            uint2* dst = reinterpret_cast<uint2*>(&Ws[row * ASTR + c8]);
            dst[0] = make_uint2(val.x, val.y);
            dst[1] = make_uint2(val.z, val.w);
        }
        __syncthreads();
        #pragma unroll
        for (int s = 0; s < 6; s++) {
            const int kb = s * 16;
            uint32_t a0 = *reinterpret_cast<const uint32_t*>(&As[(warp*16 + l4    ) * ASTR + kb + q2]);
            uint32_t a1 = *reinterpret_cast<const uint32_t*>(&As[(warp*16 + l4 + 8) * ASTR + kb + q2]);
            uint32_t a2 = *reinterpret_cast<const uint32_t*>(&As[(warp*16 + l4    ) * ASTR + kb + 8 + q2]);
            uint32_t a3 = *reinterpret_cast<const uint32_t*>(&As[(warp*16 + l4 + 8) * ASTR + kb + 8 + q2]);
            #pragma unroll
            for (int nt = 0; nt < 4; nt++) {
                uint32_t b0 = *reinterpret_cast<const uint32_t*>(&Ws[(nt*8 + l4) * ASTR + kb + q2]);
                uint32_t b1 = *reinterpret_cast<const uint32_t*>(&Ws[(nt*8 + l4) * ASTR + kb + 8 + q2]);
                mma16816(c[nt], a0, a1, a2, a3, b0, b1);
            }
        }
        __syncthreads();
    }

    const int mr = m0 + warp * 16 + l4;
    #pragma unroll
    for (int nt = 0; nt < 4; nt++) {
        int j0 = n0 + nt * 8 + q2;
        float bv0 = bias[j0], bv1 = bias[j0 + 1];
        store2<EPI>(mr,     j0, c[nt][0] + bv0, c[nt][1] + bv1, extra, outp);
        store2<EPI>(mr + 8, j0, c[nt][2] + bv0, c[nt][3] + bv1, extra, outp);
    }
}

// ---------------- HMMA windowed attention (FA2-style, warp-level) ----------------
// one block per (window, head); 8 warps; each warp owns 16-row q tiles.
#define KSTR 40      // Ks stride (halves): 20*l4 mod 32 conflict-free
#define VSTR 372     // Vt stride (halves): 372 = 20 mod 32 conflict-free
#define ATTN_SMEM (352*KSTR*2 + 24*VSTR*2 + 328*4 + 352*4)

__global__ __launch_bounds__(256)
void attn_kernel(const float* __restrict__ rpb_table)
{
    extern __shared__ char smraw[];
    __nv_bfloat16* Ks  = reinterpret_cast<__nv_bfloat16*>(smraw);             // [352][KSTR]
    __nv_bfloat16* Vt  = Ks + 352*KSTR;                                       // [24][VSTR]
    float*         rpbs = reinterpret_cast<float*>(Vt + 24*VSTR);             // [328]
    int*           pkg  = reinterpret_cast<int*>(rpbs + 328);                 // [352] grp<<10|key

    const int bh  = blockIdx.x;
    const int win = bh >> 2, h = bh & 3;
    const int tid = threadIdx.x;
    const int warp = tid >> 5, lane = tid & 31;
    const int l4 = lane >> 2, q2 = (lane & 3) * 2;
    const size_t base = (size_t)bh * (NTOK * HDIM);

    // --- stage K (zero-pad keys>=343 and dims>=24) ---
    for (int idx = tid; idx < 352 * 4; idx += 256) {
        int key = idx >> 2, d8 = (idx & 3) << 3;
        uint4 val = make_uint4(0u, 0u, 0u, 0u);
        if (key < NTOK && d8 < 24)
            val = *reinterpret_cast<const uint4*>(&g_k[base + (size_t)key * HDIM + d8]);
        *reinterpret_cast<uint4*>(&Ks[key * KSTR + d8]) = val;
    }
    // --- zero Vt pad columns (keys 343..371), then scatter-transpose V ---
    for (int idx = tid; idx < 24 * 32; idx += 256) {
        int dim = idx >> 5, key = NTOK + (idx & 31);
        if (key < VSTR) Vt[dim * VSTR + key] = __float2bfloat16(0.0f);
    }
    __syncthreads();
    for (int idx = tid; idx < NTOK * HDIM; idx += 256) {
        int key = idx / HDIM, dim = idx - key * HDIM;
        Vt[dim * VSTR + key] = g_v[base + idx];
    }
    for (int idx = tid; idx < 325; idx += 256)
        rpbs[idx] = rpb_table[idx * NHEAD + h];

    {
        int w3 = win & 63;
        int wh = w3 >> 4, ww = (w3 >> 2) & 3, wd = w3 & 3;
        for (int t = tid; t < 352; t += 256) {
            if (t < NTOK) {
                int a = t / 49, rr = t - a * 49, bb = rr / 7, cc = rr - bb * 7;
                int key = 13 * (a + bb) + cc;
                int gh = wh * 7 + a, gw = ww * 7 + bb, gd = wd * 7 + cc;
                int sg = ((gh >= 21) + (gh >= 25)) * 9
                       + ((gw >= 21) + (gw >= 25)) * 3
                       + ((gd >= 21) + (gd >= 25));
                pkg[t] = (sg << 10) | key;
            } else {
                pkg[t] = (100 << 10);   // sentinel: mismatches all groups, key=0
            }
        }
    }
    __syncthreads();

    // --- per-warp q tiles ---
    for (int tile = warp; tile < 22; tile += 8) {
        const int row0 = tile * 16 + l4, row1 = row0 + 8;
        const int r0c = row0 < NTOK ? row0 : NTOK - 1;
        const int r1c = row1 < NTOK ? row1 : NTOK - 1;

        // Q fragments (held in regs across all key blocks)
        uint32_t qa00, qa01, qa02, qa03, qa10, qa11;
        {
            const __nv_bfloat16* q0 = g_q + base + (size_t)r0c * HDIM;
            const __nv_bfloat16* q1 = g_q + base + (size_t)r1c * HDIM;
            qa00 = *reinterpret_cast<const uint32_t*>(q0 + q2);
            qa01 = *reinterpret_cast<const uint32_t*>(q1 + q2);
            qa02 = *reinterpret_cast<const uint32_t*>(q0 + 8 + q2);
            qa03 = *reinterpret_cast<const uint32_t*>(q1 + 8 + q2);
            qa10 = *reinterpret_cast<const uint32_t*>(q0 + 16 + q2);
            qa11 = *reinterpret_cast<const uint32_t*>(q1 + 16 + q2);
        }
        const int pkg0 = pkg[r0c], pkg1 = pkg[r1c];
        const int keyi0 = (pkg0 & 1023) + 162, g0 = pkg0 >> 10;
        const int keyi1 = (pkg1 & 1023) + 162, g1 = pkg1 >> 10;

        float m0 = -1e30f, m1 = -1e30f, sum0 = 0.0f, sum1 = 0.0f;
        float o[3][4] = {};

        for (int kb = 0; kb < 352; kb += 32) {
            // S = Q K^T for this 16x32 block
            float c[4][4] = {};
            #pragma unroll
            for (int nt = 0; nt < 4; nt++) {
                const __nv_bfloat16* kr = &Ks[(kb + nt * 8 + l4) * KSTR];
                uint32_t b0 = *reinterpret_cast<const uint32_t*>(kr + q2);
                uint32_t b1 = *reinterpret_cast<const uint32_t*>(kr + 8 + q2);
                mma16816(c[nt], qa00, qa01, qa02, qa03, b0, b1);
                uint32_t b2 = *reinterpret_cast<const uint32_t*>(kr + 16 + q2);
                uint32_t b3 = *reinterpret_cast<const uint32_t*>(kr + 24 + q2);
                mma16816(c[nt], qa10, qa11, 0u, 0u, b2, b3);
            }
            // rpb + mask, block row-max
            float bm0 = -1e30f, bm1 = -1e30f;
            #pragma unroll
            for (int nt = 0; nt < 4; nt++) {
                #pragma unroll
                for (int e = 0; e < 2; e++) {
                    int key = kb + nt * 8 + q2 + e;
                    int pv = pkg[key];
                    int pk = pv & 1023, gk = pv >> 10;
                    float s0 = c[nt][e]     + rpbs[keyi0 - pk] + (gk == g0 ? 0.0f : -100.0f);
                    float s1 = c[nt][2 + e] + rpbs[keyi1 - pk] + (gk == g1 ? 0.0f : -100.0f);
                    c[nt][e] = s0; c[nt][2 + e] = s1;
                    bm0 = fmaxf(bm0, s0); bm1 = fmaxf(bm1, s1);
                }
            }
            bm0 = fmaxf(bm0, __shfl_xor_sync(0xffffffffu, bm0, 1));
            bm0 = fmaxf(bm0, __shfl_xor_sync(0xffffffffu, bm0, 2));
            bm1 = fmaxf(bm1, __shfl_xor_sync(0xffffffffu, bm1, 1));
            bm1 = fmaxf(bm1, __shfl_xor_sync(0xffffffffu, bm1, 2));
            float M0 = fmaxf(m0, bm0), M1 = fmaxf(m1, bm1);
            float al0 = __expf(m0 - M0), al1 = __expf(m1 - M1);
            m0 = M0; m1 = M1;
            sum0 *= al0; sum1 *= al1;
            #pragma unroll
            for (int nt = 0; nt < 3; nt++) {
                o[nt][0] *= al0; o[nt][1] *= al0;
                o[nt][2] *= al1; o[nt][3] *= al1;
            }
            // P = exp(S - M), packed into A fragments
            uint32_t pa[2][4];
            #pragma unroll
            for (int nt = 0; nt < 4; nt++) {
                float p0 = __expf(c[nt][0] - M0), p1 = __expf(c[nt][1] - M0);
                float p2 = __expf(c[nt][2] - M1), p3 = __expf(c[nt][3] - M1);
                sum0 += p0 + p1; sum1 += p2 + p3;
                __nv_bfloat162 h01 = __float22bfloat162_rn(make_float2(p0, p1));
                __nv_bfloat162 h23 = __float22bfloat162_rn(make_float2(p2, p3));
                pa[nt >> 1][(nt & 1) * 2 + 0] = *reinterpret_cast<uint32_t*>(&h01);
                pa[nt >> 1][(nt & 1) * 2 + 1] = *reinterpret_cast<uint32_t*>(&h23);
            }
            // O += P V
            #pragma unroll
            for (int ks = 0; ks < 2; ks++) {
                #pragma unroll
                for (int nt = 0; nt < 3; nt++) {
                    const __nv_bfloat16* vr = &Vt[(nt * 8 + l4) * VSTR + kb + ks * 16];
                    uint32_t b0 = *reinterpret_cast<const uint32_t*>(vr + q2);
                    uint32_t b1 = *reinterpret_cast<const uint32_t*>(vr + 8 + q2);
                    mma16816(o[nt], pa[ks][0], pa[ks][1], pa[ks][2], pa[ks][3], b0, b1);
                }
            }
        }
        sum0 += __shfl_xor_sync(0xffffffffu, sum0, 1);
        sum0 += __shfl_xor_sync(0xffffffffu, sum0, 2);
        sum1 += __shfl_xor_sync(0xffffffffu, sum1, 1);
        sum1 += __shfl_xor_sync(0xffffffffu, sum1, 2);
        float inv0 = 1.0f / sum0, inv1 = 1.0f / sum1;

        if (row0 < NTOK) {
            __nv_bfloat16* op = g_ao + ((size_t)win * NTOK + row0) * CDIM + h * HDIM;
            #pragma unroll
            for (int nt = 0; nt < 3; nt++)
                *reinterpret_cast<__nv_bfloat162*>(op + nt * 8 + q2) =
                    __float22bfloat162_rn(make_float2(o[nt][0] * inv0, o[nt][1] * inv0));
        }
        if (row1 < NTOK) {
            __nv_bfloat16* op = g_ao + ((size_t)win * NTOK + row1) * CDIM + h * HDIM;
            #pragma unroll
            for (int nt = 0; nt < 3; nt++)
                *reinterpret_cast<__nv_bfloat162*>(op + nt * 8 + q2) =
                    __float22bfloat162_rn(make_float2(o[nt][2] * inv1, o[nt][3] * inv1));
        }
    }
}

// ---------------- launch ----------------
extern "C" void kernel_launch(void* const* d_in, const int* in_sizes, int n_in,
                              void* d_out, int out_size)
{
    const float* x    = (const float*)d_in[0];
    const float* n1w  = (const float*)d_in[1];
    const float* n1b  = (const float*)d_in[2];
    const float* qkvw = (const float*)d_in[3];
    const float* qkvb = (const float*)d_in[4];
    const float* rpb  = (const float*)d_in[5];
    const float* pw   = (const float*)d_in[6];
    const float* pb   = (const float*)d_in[7];
    const float* n2w  = (const float*)d_in[8];
    const float* n2b  = (const float*)d_in[9];
    const float* f1w  = (const float*)d_in[10];
    const float* f1b  = (const float*)d_in[11];
    const float* f2w  = (const float*)d_in[12];
    const float* f2b  = (const float*)d_in[13];
    float* out = (float*)d_out;

    cudaFuncSetAttribute(attn_kernel, cudaFuncAttributeMaxDynamicSharedMemorySize, ATTN_SMEM);

    prep_weights<<<144, 256>>>(qkvw, pw, f1w, f2w);
    ln1_kernel<<<MTOT / 8, 256>>>(x, n1w, n1b);
    hgemm_kernel<EPI_QKV, 96, 288><<<dim3(686, 9), 256>>>(qkvb, nullptr, nullptr);
    attn_kernel<<<NWINS * NHEAD, 256, ATTN_SMEM>>>(rpb);
    hgemm_kernel<EPI_PROJ, 96, 96><<<dim3(686, 3), 256>>>(pb, x, nullptr);
    ln2_kernel<<<MTOT / 8, 256>>>(n2w, n2b);
    hgemm_kernel<EPI_GELU, 96, 384><<<dim3(686, 12), 256>>>(f1b, nullptr, nullptr);
    hgemm_kernel<EPI_FC2, 384, 96><<<dim3(686, 3), 256>>>(f2b, nullptr, out);
}